// round 2
// baseline (speedup 1.0000x reference)
#include <cuda_runtime.h>
#include <math.h>

#define BB   4
#define NY   16384
#define NX   4096
#define CY   128
#define CX   256
#define DIM  384
#define C1   512
#define C2   256
#define C3   128
#define NTOT (BB*NY)   // 65536

// ---------------- scratch (static device allocations) ----------------
__device__ float4 g_xpack[BB*NX];
__device__ int    g_nbi[NTOT*3];
__device__ float  g_nbw[NTOT*3];
__device__ float  g_F0[(size_t)NTOT*DIM];
__device__ float  g_Z1[(size_t)NTOT*C1];
__device__ float  g_Z2[(size_t)NTOT*C2];
__device__ float  g_Z3[(size_t)NTOT*C3];
__device__ double g_stats1[2*C1];
__device__ double g_stats2[2*C2];
__device__ double g_stats3[2*C3];
__device__ float  g_ab1[2*C1];
__device__ float  g_ab2[2*C2];
__device__ float  g_ab3[2*C3];

// ---------------- pack x points + zero stats ----------------
// |x|^2 computed as ((x0*x0 + x1*x1) + x2*x2), mul/add separate (match XLA reduce)
__global__ void k_pack(const float* __restrict__ xp) {
    int i = blockIdx.x * 256 + threadIdx.x;
    if (i < BB*NX) {
        float x = xp[i*3+0], y = xp[i*3+1], z = xp[i*3+2];
        float sx = __fadd_rn(__fadd_rn(__fmul_rn(x,x), __fmul_rn(y,y)), __fmul_rn(z,z));
        g_xpack[i] = make_float4(x, y, z, sx);
    }
    if (i < 2*C1) g_stats1[i] = 0.0;
    else if (i < 2*C1 + 2*C2) g_stats2[i - 2*C1] = 0.0;
    else if (i < 2*C1 + 2*C2 + 2*C3) g_stats3[i - 2*C1 - 2*C2] = 0.0;
}

// ---------------- 3-NN search (replicating reference arithmetic order) ----------------
// d = (|y|^2 + |x|^2) - 2*dot,  dot = fma(y2,x2, fma(y1,x1, y0*x0))
__global__ void k_knn(const float* __restrict__ yp) {
    __shared__ float4 sx[2048];
    int b = blockIdx.y;
    int n = b * NY + blockIdx.x * blockDim.x + threadIdx.x;
    float yx = yp[n*3+0], yy = yp[n*3+1], yz = yp[n*3+2];
    float sy = __fadd_rn(__fadd_rn(__fmul_rn(yx,yx), __fmul_rn(yy,yy)), __fmul_rn(yz,yz));
    float k0 = 1e30f, k1 = 1e30f, k2 = 1e30f;
    int   i0 = 0, i1 = 0, i2 = 0;

    for (int base = 0; base < NX; base += 2048) {
        __syncthreads();
        for (int i = threadIdx.x; i < 2048; i += blockDim.x)
            sx[i] = g_xpack[b*NX + base + i];
        __syncthreads();
        #pragma unroll 4
        for (int j = 0; j < 2048; j++) {
            float4 p = sx[j];
            float dot = __fmaf_rn(yz, p.z, __fmaf_rn(yy, p.y, __fmul_rn(yx, p.x)));
            float d = __fadd_rn(__fadd_rn(sy, p.w), -__fmul_rn(2.0f, dot));
            if (d < k2) {
                int jj = base + j;
                if (d < k1) {
                    k2 = k1; i2 = i1;
                    if (d < k0) { k1 = k0; i1 = i0; k0 = d; i0 = jj; }
                    else        { k1 = d; i1 = jj; }
                } else { k2 = d; i2 = jj; }
            }
        }
    }
    // weights exactly as reference: w = 1/(d+eps); w /= (w0+w1)+w2
    float w0 = __fdiv_rn(1.0f, __fadd_rn(k0, 1e-8f));
    float w1 = __fdiv_rn(1.0f, __fadd_rn(k1, 1e-8f));
    float w2 = __fdiv_rn(1.0f, __fadd_rn(k2, 1e-8f));
    float sw = __fadd_rn(__fadd_rn(w0, w1), w2);
    g_nbi[n*3+0] = i0; g_nbi[n*3+1] = i1; g_nbi[n*3+2] = i2;
    g_nbw[n*3+0] = __fdiv_rn(w0, sw);
    g_nbw[n*3+1] = __fdiv_rn(w1, sw);
    g_nbw[n*3+2] = __fdiv_rn(w2, sw);
}

// ---------------- gather + interpolate + concat -> F0 [N,384] ----------------
__global__ void k_gather(const float* __restrict__ yf, const float* __restrict__ xf) {
    int n = blockIdx.x;
    int t = threadIdx.x;
    int b = n >> 14;   // n / NY
    float* o = g_F0 + (size_t)n * DIM;
    o[t] = yf[(size_t)n * CY + t];
    int i0 = g_nbi[n*3+0], i1 = g_nbi[n*3+1], i2 = g_nbi[n*3+2];
    float w0 = g_nbw[n*3+0], w1 = g_nbw[n*3+1], w2 = g_nbw[n*3+2];
    const float* r0 = xf + ((size_t)(b*NX + i0)) * CX;
    const float* r1 = xf + ((size_t)(b*NX + i1)) * CX;
    const float* r2 = xf + ((size_t)(b*NX + i2)) * CX;
    // ((f0*w0 + f1*w1) + f2*w2), mul/add separate (match XLA sum over K axis)
    o[CY + t] = __fadd_rn(__fadd_rn(__fmul_rn(r0[t], w0), __fmul_rn(r1[t], w1)),
                          __fmul_rn(r2[t], w2));
    o[CY + 128 + t] = __fadd_rn(__fadd_rn(__fmul_rn(r0[128+t], w0), __fmul_rn(r1[128+t], w1)),
                                __fmul_rn(r2[128+t], w2));
}

// ---------------- GEMM: Z[n,c] = act(A)[n,:] . W[c,:] + bias[c]; + BN stats ----------------
template<int Kd, int Cout, bool ACT>
__global__ void __launch_bounds__(256)
k_gemm(const float* __restrict__ A, const float* __restrict__ W,
       const float* __restrict__ bias, const float* __restrict__ ab,
       float* __restrict__ Z, double* __restrict__ stats)
{
    const int S = 132;                 // smem row stride (floats), 16B-aligned
    __shared__ float As[16*S];
    __shared__ float Ws[16*S];
    __shared__ float sSum[128], sSq[128];

    int tid = threadIdx.x;
    int tx = tid & 15, ty = tid >> 4;
    int n0 = blockIdx.x * 128;
    int c0 = blockIdx.y * 128;
    if (tid < 128) { sSum[tid] = 0.f; sSq[tid] = 0.f; }

    float acc[8][8];
    #pragma unroll
    for (int i = 0; i < 8; i++)
        #pragma unroll
        for (int j = 0; j < 8; j++) acc[i][j] = 0.f;

    int lr  = tid >> 1;          // tile row 0..127
    int kb  = (tid & 1) * 8;     // k offset within tile: 0 or 8

    for (int kt = 0; kt < Kd; kt += 16) {
        __syncthreads();
        {   // A tile (with fused BN+ReLU of previous layer)
            const float* src = A + (size_t)(n0 + lr) * Kd + kt + kb;
            float4 v0 = *(const float4*)(src);
            float4 v1 = *(const float4*)(src + 4);
            if (ACT) {
                float4 a0 = *(const float4*)(ab + kt + kb);
                float4 a1 = *(const float4*)(ab + kt + kb + 4);
                float4 s0 = *(const float4*)(ab + Kd + kt + kb);
                float4 s1 = *(const float4*)(ab + Kd + kt + kb + 4);
                v0.x = fmaxf(fmaf(a0.x, v0.x, s0.x), 0.f);
                v0.y = fmaxf(fmaf(a0.y, v0.y, s0.y), 0.f);
                v0.z = fmaxf(fmaf(a0.z, v0.z, s0.z), 0.f);
                v0.w = fmaxf(fmaf(a0.w, v0.w, s0.w), 0.f);
                v1.x = fmaxf(fmaf(a1.x, v1.x, s1.x), 0.f);
                v1.y = fmaxf(fmaf(a1.y, v1.y, s1.y), 0.f);
                v1.z = fmaxf(fmaf(a1.z, v1.z, s1.z), 0.f);
                v1.w = fmaxf(fmaf(a1.w, v1.w, s1.w), 0.f);
            }
            As[(kb+0)*S + lr] = v0.x; As[(kb+1)*S + lr] = v0.y;
            As[(kb+2)*S + lr] = v0.z; As[(kb+3)*S + lr] = v0.w;
            As[(kb+4)*S + lr] = v1.x; As[(kb+5)*S + lr] = v1.y;
            As[(kb+6)*S + lr] = v1.z; As[(kb+7)*S + lr] = v1.w;
        }
        {   // W tile
            const float* src = W + (size_t)(c0 + lr) * Kd + kt + kb;
            float4 v0 = *(const float4*)(src);
            float4 v1 = *(const float4*)(src + 4);
            Ws[(kb+0)*S + lr] = v0.x; Ws[(kb+1)*S + lr] = v0.y;
            Ws[(kb+2)*S + lr] = v0.z; Ws[(kb+3)*S + lr] = v0.w;
            Ws[(kb+4)*S + lr] = v1.x; Ws[(kb+5)*S + lr] = v1.y;
            Ws[(kb+6)*S + lr] = v1.z; Ws[(kb+7)*S + lr] = v1.w;
        }
        __syncthreads();
        #pragma unroll
        for (int kk = 0; kk < 16; kk++) {
            float a[8], w[8];
            *(float4*)&a[0] = *(const float4*)&As[kk*S + ty*8];
            *(float4*)&a[4] = *(const float4*)&As[kk*S + ty*8 + 4];
            *(float4*)&w[0] = *(const float4*)&Ws[kk*S + tx*8];
            *(float4*)&w[4] = *(const float4*)&Ws[kk*S + tx*8 + 4];
            #pragma unroll
            for (int i = 0; i < 8; i++)
                #pragma unroll
                for (int j = 0; j < 8; j++)
                    acc[i][j] = fmaf(a[i], w[j], acc[i][j]);
        }
    }

    // epilogue: bias, store, per-channel sum/sumsq
    float bj[8], bsum[8], bsq[8];
    #pragma unroll
    for (int j = 0; j < 8; j++) { bj[j] = bias[c0 + tx*8 + j]; bsum[j] = 0.f; bsq[j] = 0.f; }
    #pragma unroll
    for (int i = 0; i < 8; i++) {
        int row = n0 + ty*8 + i;
        float v[8];
        #pragma unroll
        for (int j = 0; j < 8; j++) {
            v[j] = acc[i][j] + bj[j];
            bsum[j] += v[j];
            bsq[j]  = fmaf(v[j], v[j], bsq[j]);
        }
        float4* dst = (float4*)(Z + (size_t)row * Cout + c0 + tx*8);
        dst[0] = make_float4(v[0], v[1], v[2], v[3]);
        dst[1] = make_float4(v[4], v[5], v[6], v[7]);
    }
    #pragma unroll
    for (int j = 0; j < 8; j++) {
        atomicAdd(&sSum[tx*8+j], bsum[j]);
        atomicAdd(&sSq[tx*8+j],  bsq[j]);
    }
    __syncthreads();
    if (tid < 128) {
        atomicAdd(&stats[c0 + tid],        (double)sSum[tid]);
        atomicAdd(&stats[Cout + c0 + tid], (double)sSq[tid]);
    }
}

// ---------------- fold BN into a*z + b (double precision stats) ----------------
__global__ void k_bnprep(const double* __restrict__ st, const float* __restrict__ g,
                         const float* __restrict__ be, float* __restrict__ ab, int C) {
    int c = threadIdx.x;
    if (c < C) {
        double mu  = st[c] * (1.0/NTOT);
        double var = st[C + c] * (1.0/NTOT) - mu*mu;
        float a = g[c] * (float)(1.0 / sqrt(var + 1e-5));
        ab[c]     = a;
        ab[C + c] = fmaf((float)(-mu), a, be[c]);
    }
}

// ---------------- final BN3+ReLU + transpose to [B,128,NY] ----------------
__global__ void k_out(float* __restrict__ out) {
    __shared__ float t[32][33];
    int n0 = blockIdx.x * 32;
    int c0 = blockIdx.y * 32;
    int tx = threadIdx.x, ty = threadIdx.y;    // (32, 8)
    float a  = g_ab3[c0 + tx];
    float sh = g_ab3[C3 + c0 + tx];
    #pragma unroll
    for (int i = 0; i < 32; i += 8) {
        float z = g_Z3[(size_t)(n0 + ty + i) * C3 + c0 + tx];
        t[ty + i][tx] = fmaxf(fmaf(a, z, sh), 0.f);
    }
    __syncthreads();
    int b  = n0 >> 14;        // n0 / NY
    int nl = n0 & (NY - 1);
    #pragma unroll
    for (int i = 0; i < 32; i += 8) {
        int c = c0 + ty + i;
        out[((size_t)b * C3 + c) * NY + nl + tx] = t[tx][ty + i];
    }
}

// ---------------- launch ----------------
extern "C" void kernel_launch(void* const* d_in, const int* in_sizes, int n_in,
                              void* d_out, int out_size) {
    (void)in_sizes; (void)n_in; (void)out_size;
    const float* y_points = (const float*)d_in[0];
    const float* y_feats  = (const float*)d_in[1];
    const float* x_points = (const float*)d_in[2];
    const float* x_feats  = (const float*)d_in[3];
    const float* W1  = (const float*)d_in[4];
    const float* b1  = (const float*)d_in[5];
    const float* g1  = (const float*)d_in[6];
    const float* be1 = (const float*)d_in[7];
    const float* W2  = (const float*)d_in[8];
    const float* b2  = (const float*)d_in[9];
    const float* g2  = (const float*)d_in[10];
    const float* be2 = (const float*)d_in[11];
    const float* W3  = (const float*)d_in[12];
    const float* b3  = (const float*)d_in[13];
    const float* g3  = (const float*)d_in[14];
    const float* be3 = (const float*)d_in[15];
    float* out = (float*)d_out;

    float *pF0, *pZ1, *pZ2, *pZ3, *pAb1, *pAb2, *pAb3;
    double *pSt1, *pSt2, *pSt3;
    cudaGetSymbolAddress((void**)&pF0,  g_F0);
    cudaGetSymbolAddress((void**)&pZ1,  g_Z1);
    cudaGetSymbolAddress((void**)&pZ2,  g_Z2);
    cudaGetSymbolAddress((void**)&pZ3,  g_Z3);
    cudaGetSymbolAddress((void**)&pSt1, g_stats1);
    cudaGetSymbolAddress((void**)&pSt2, g_stats2);
    cudaGetSymbolAddress((void**)&pSt3, g_stats3);
    cudaGetSymbolAddress((void**)&pAb1, g_ab1);
    cudaGetSymbolAddress((void**)&pAb2, g_ab2);
    cudaGetSymbolAddress((void**)&pAb3, g_ab3);

    k_pack<<<64, 256>>>(x_points);
    k_knn<<<dim3(NY/256, BB), 256>>>(y_points);
    k_gather<<<NTOT, 128>>>(y_feats, x_feats);

    k_gemm<DIM, C1, false><<<dim3(NTOT/128, C1/128), 256>>>(pF0, W1, b1, nullptr, pZ1, pSt1);
    k_bnprep<<<1, C1>>>(pSt1, g1, be1, pAb1, C1);

    k_gemm<C1, C2, true><<<dim3(NTOT/128, C2/128), 256>>>(pZ1, W2, b2, pAb1, pZ2, pSt2);
    k_bnprep<<<1, C2>>>(pSt2, g2, be2, pAb2, C2);

    k_gemm<C2, C3, true><<<dim3(NTOT/128, C3/128), 256>>>(pZ2, W3, b3, pAb2, pZ3, pSt3);
    k_bnprep<<<1, C3>>>(pSt3, g3, be3, pAb3, C3);

    k_out<<<dim3(NTOT/32, C3/32), dim3(32, 8)>>>(out);
}